// round 1
// baseline (speedup 1.0000x reference)
#include <cuda_runtime.h>
#include <cstdint>

#define SIZE  4096
#define NDOWN 256
#define NT    16
#define MAXB  4096

// ---------------- device scratch (no allocs allowed) ----------------
__device__ int   g_offsets[NT + 1];
__device__ int   g_sorted[MAXB];
__device__ int   g_workD_t[MAXB / 64 + NT + 1];
__device__ int   g_workD_m0[MAXB / 64 + NT + 1];
__device__ int   g_nworkD;
__device__ int   g_workU_t[MAXB / 128 + NT + 1];
__device__ int   g_workU_m0[MAXB / 128 + NT + 1];
__device__ int   g_nworkU;
__device__ float g_act[(size_t)MAXB * NDOWN];

// ---------------- helpers ----------------
__device__ __forceinline__ uint32_t smem_u32(const void* p) {
    return (uint32_t)__cvta_generic_to_shared(p);
}

__device__ __forceinline__ void cp_async16(uint32_t dst, const void* src, bool pred) {
    int sz = pred ? 16 : 0;
    asm volatile("cp.async.cg.shared.global [%0], [%1], 16, %2;\n"
                 :: "r"(dst), "l"(src), "r"(sz) : "memory");
}
__device__ __forceinline__ void cp_commit() {
    asm volatile("cp.async.commit_group;\n" ::: "memory");
}
__device__ __forceinline__ void cp_wait1() {
    asm volatile("cp.async.wait_group 1;\n" ::: "memory");
}

__device__ __forceinline__ void mma_tf32(float& c0, float& c1, float& c2, float& c3,
                                         uint32_t a0, uint32_t a1, uint32_t a2, uint32_t a3,
                                         uint32_t b0, uint32_t b1) {
    asm volatile(
        "mma.sync.aligned.m16n8k8.row.col.f32.tf32.tf32.f32 "
        "{%0,%1,%2,%3}, {%4,%5,%6,%7}, {%8,%9}, {%0,%1,%2,%3};\n"
        : "+f"(c0), "+f"(c1), "+f"(c2), "+f"(c3)
        : "r"(a0), "r"(a1), "r"(a2), "r"(a3), "r"(b0), "r"(b1));
}

// ---------------- phase A: counting sort by task + worklists ----------------
__global__ void prep_kernel(const int* __restrict__ task_id, int B) {
    __shared__ int cnt[NT];
    __shared__ int off[NT + 1];
    __shared__ int cur[NT];
    int tid = threadIdx.x;
    if (tid < NT) cnt[tid] = 0;
    __syncthreads();
    for (int i = tid; i < B; i += blockDim.x)
        atomicAdd(&cnt[task_id[i]], 1);
    __syncthreads();
    if (tid == 0) {
        int s = 0;
        for (int t = 0; t < NT; t++) { off[t] = s; s += cnt[t]; }
        off[NT] = s;
        int nw = 0;
        for (int t = 0; t < NT; t++)
            for (int m = off[t]; m < off[t + 1]; m += 64) {
                g_workD_t[nw] = t; g_workD_m0[nw] = m; nw++;
            }
        g_nworkD = nw;
        nw = 0;
        for (int t = 0; t < NT; t++)
            for (int m = off[t]; m < off[t + 1]; m += 128) {
                g_workU_t[nw] = t; g_workU_m0[nw] = m; nw++;
            }
        g_nworkU = nw;
    }
    __syncthreads();
    if (tid <= NT) g_offsets[tid] = off[tid];
    if (tid < NT)  cur[tid] = off[tid];
    __syncthreads();
    for (int i = tid; i < B; i += blockDim.x) {
        int p = atomicAdd(&cur[task_id[i]], 1);
        g_sorted[p] = i;
    }
}

// ---------------- phase B: down-proj + silu (grouped GEMM, tf32 mma) ----------
// Tile: 64(M) x 64(N) x 32(K), 128 threads = 4 warps (2x2 of 32x32 warp tiles),
// 3-stage cp.async pipeline. A rows gathered via g_sorted; result -> g_act.
#define D_ASTRIDE 36   // 32 + 4  (stride mod 32 == 4 -> conflict-free A frag LDS)
#define D_BSTRIDE 72   // 64 + 8  (stride mod 32 == 8 -> conflict-free B frag LDS)
#define D_STAGES  3

__global__ void __launch_bounds__(128) down_kernel(const float* __restrict__ x,
                                                   const float* __restrict__ Wd,
                                                   const float* __restrict__ bd,
                                                   int B) {
    if ((int)blockIdx.y >= g_nworkD) return;
    const int t    = g_workD_t[blockIdx.y];
    const int m0   = g_workD_m0[blockIdx.y];
    const int rows = min(64, g_offsets[t + 1] - m0);
    const int n0   = blockIdx.x * 64;

    extern __shared__ float smem[];
    float* As = smem;                                // [3][64][36]
    float* Bs = smem + D_STAGES * 64 * D_ASTRIDE;    // [3][32][72]
    __shared__ int s_idx[64];

    const int tid = threadIdx.x;
    if (tid < 64) s_idx[tid] = (tid < rows) ? g_sorted[m0 + tid] : -1;
    __syncthreads();

    const uint32_t aU = smem_u32(As);
    const uint32_t bU = smem_u32(Bs);
    const size_t   wbase = (size_t)t * SIZE * NDOWN + n0;

    auto load_stage = [&](int s, int kt) {
        const int k0 = kt * 32;
#pragma unroll
        for (int i = 0; i < 4; i++) {
            int f = tid + i * 128;
            int r = f >> 3, kc = (f & 7) << 2;
            int idx = s_idx[r];
            const float* src = x + (size_t)(idx < 0 ? 0 : idx) * SIZE + (k0 + kc);
            cp_async16(aU + (uint32_t)(((s * 64 + r) * D_ASTRIDE + kc) * 4), src, idx >= 0);
        }
#pragma unroll
        for (int i = 0; i < 4; i++) {
            int f = tid + i * 128;
            int r = f >> 4, nc = (f & 15) << 2;
            const float* src = Wd + wbase + (size_t)(k0 + r) * NDOWN + nc;
            cp_async16(bU + (uint32_t)(((s * 32 + r) * D_BSTRIDE + nc) * 4), src, true);
        }
        cp_commit();
    };

    float c[2][4][4] = {};
    const int lane = tid & 31, wid = tid >> 5;
    const int g = lane >> 2, tg = lane & 3;
    const int wm = wid >> 1, wn = wid & 1;

    const int NIT = SIZE / 32;  // 128
    load_stage(0, 0);
    load_stage(1, 1);

    for (int it = 0; it < NIT; ++it) {
        cp_wait1();
        __syncthreads();
        const int buf = it % D_STAGES;
        const float* A  = As + buf * 64 * D_ASTRIDE;
        const float* Bt = Bs + buf * 32 * D_BSTRIDE;
        if (it + 2 < NIT) load_stage((it + 2) % D_STAGES, it + 2);
        else              cp_commit();  // keep group arithmetic aligned
#pragma unroll
        for (int ks = 0; ks < 4; ++ks) {
            uint32_t a[2][4], b[4][2];
            const int k = ks * 8 + tg;
#pragma unroll
            for (int mi = 0; mi < 2; mi++) {
                int r = wm * 32 + mi * 16 + g;
                a[mi][0] = __float_as_uint(A[r * D_ASTRIDE + k]);
                a[mi][1] = __float_as_uint(A[(r + 8) * D_ASTRIDE + k]);
                a[mi][2] = __float_as_uint(A[r * D_ASTRIDE + k + 4]);
                a[mi][3] = __float_as_uint(A[(r + 8) * D_ASTRIDE + k + 4]);
            }
#pragma unroll
            for (int ni = 0; ni < 4; ni++) {
                int n = wn * 32 + ni * 8 + g;
                b[ni][0] = __float_as_uint(Bt[k * D_BSTRIDE + n]);
                b[ni][1] = __float_as_uint(Bt[(k + 4) * D_BSTRIDE + n]);
            }
#pragma unroll
            for (int mi = 0; mi < 2; mi++)
#pragma unroll
                for (int ni = 0; ni < 4; ni++)
                    mma_tf32(c[mi][ni][0], c[mi][ni][1], c[mi][ni][2], c[mi][ni][3],
                             a[mi][0], a[mi][1], a[mi][2], a[mi][3],
                             b[ni][0], b[ni][1]);
        }
    }

    // epilogue: + bd, silu, store to g_act (sorted order)
    const float* bdp = bd + t * NDOWN + n0;
#pragma unroll
    for (int mi = 0; mi < 2; mi++) {
        int r0 = wm * 32 + mi * 16 + g;
#pragma unroll
        for (int ni = 0; ni < 4; ni++) {
            int col = wn * 32 + ni * 8 + tg * 2;
            float b0 = bdp[col], b1 = bdp[col + 1];
            if (r0 < rows) {
                float d0 = c[mi][ni][0] + b0, d1 = c[mi][ni][1] + b1;
                g_act[(size_t)(m0 + r0) * NDOWN + n0 + col]     = d0 / (1.f + __expf(-d0));
                g_act[(size_t)(m0 + r0) * NDOWN + n0 + col + 1] = d1 / (1.f + __expf(-d1));
            }
            int r1 = r0 + 8;
            if (r1 < rows) {
                float d2 = c[mi][ni][2] + b0, d3 = c[mi][ni][3] + b1;
                g_act[(size_t)(m0 + r1) * NDOWN + n0 + col]     = d2 / (1.f + __expf(-d2));
                g_act[(size_t)(m0 + r1) * NDOWN + n0 + col + 1] = d3 / (1.f + __expf(-d3));
            }
        }
    }
}

// ---------------- phase C: up-proj + bias + residual --------------------------
// Tile: 128(M) x 128(N) x 32(K), 256 threads = 8 warps (4x2 of 32x64 warp tiles).
#define U_ASTRIDE 36    // 32 + 4
#define U_BSTRIDE 136   // 128 + 8
#define U_STAGES  3

__global__ void __launch_bounds__(256) up_kernel(const float* __restrict__ x,
                                                 const float* __restrict__ Wu,
                                                 const float* __restrict__ bu,
                                                 float* __restrict__ out,
                                                 int B) {
    if ((int)blockIdx.y >= g_nworkU) return;
    const int t    = g_workU_t[blockIdx.y];
    const int m0   = g_workU_m0[blockIdx.y];
    const int rows = min(128, g_offsets[t + 1] - m0);
    const int n0   = blockIdx.x * 128;

    extern __shared__ float smem[];
    float* As = smem;                                 // [3][128][36]
    float* Bs = smem + U_STAGES * 128 * U_ASTRIDE;    // [3][32][136]
    __shared__ int s_orig[128];

    const int tid = threadIdx.x;
    if (tid < 128) s_orig[tid] = (tid < rows) ? g_sorted[m0 + tid] : 0;

    const uint32_t aU = smem_u32(As);
    const uint32_t bU = smem_u32(Bs);
    const size_t   wbase = (size_t)t * NDOWN * SIZE + n0;

    auto load_stage = [&](int s, int kt) {
        const int k0 = kt * 32;
#pragma unroll
        for (int i = 0; i < 4; i++) {
            int f = tid + i * 256;
            int r = f >> 3, kc = (f & 7) << 2;
            const float* src = g_act + (size_t)(m0 + r) * NDOWN + (k0 + kc);
            cp_async16(aU + (uint32_t)(((s * 128 + r) * U_ASTRIDE + kc) * 4), src, true);
        }
#pragma unroll
        for (int i = 0; i < 4; i++) {
            int f = tid + i * 256;
            int r = f >> 5, nc = (f & 31) << 2;
            const float* src = Wu + wbase + (size_t)(k0 + r) * SIZE + nc;
            cp_async16(bU + (uint32_t)(((s * 32 + r) * U_BSTRIDE + nc) * 4), src, true);
        }
        cp_commit();
    };

    float c[2][8][4] = {};
    const int lane = tid & 31, wid = tid >> 5;
    const int g = lane >> 2, tg = lane & 3;
    const int wm = wid >> 1, wn = wid & 1;

    const int NIT = NDOWN / 32;  // 8
    load_stage(0, 0);
    load_stage(1, 1);

    for (int it = 0; it < NIT; ++it) {
        cp_wait1();
        __syncthreads();
        const int buf = it % U_STAGES;
        const float* A  = As + buf * 128 * U_ASTRIDE;
        const float* Bt = Bs + buf * 32 * U_BSTRIDE;
        if (it + 2 < NIT) load_stage((it + 2) % U_STAGES, it + 2);
        else              cp_commit();
#pragma unroll
        for (int ks = 0; ks < 4; ++ks) {
            uint32_t a[2][4], b[8][2];
            const int k = ks * 8 + tg;
#pragma unroll
            for (int mi = 0; mi < 2; mi++) {
                int r = wm * 32 + mi * 16 + g;
                a[mi][0] = __float_as_uint(A[r * U_ASTRIDE + k]);
                a[mi][1] = __float_as_uint(A[(r + 8) * U_ASTRIDE + k]);
                a[mi][2] = __float_as_uint(A[r * U_ASTRIDE + k + 4]);
                a[mi][3] = __float_as_uint(A[(r + 8) * U_ASTRIDE + k + 4]);
            }
#pragma unroll
            for (int ni = 0; ni < 8; ni++) {
                int n = wn * 64 + ni * 8 + g;
                b[ni][0] = __float_as_uint(Bt[k * U_BSTRIDE + n]);
                b[ni][1] = __float_as_uint(Bt[(k + 4) * U_BSTRIDE + n]);
            }
#pragma unroll
            for (int mi = 0; mi < 2; mi++)
#pragma unroll
                for (int ni = 0; ni < 8; ni++)
                    mma_tf32(c[mi][ni][0], c[mi][ni][1], c[mi][ni][2], c[mi][ni][3],
                             a[mi][0], a[mi][1], a[mi][2], a[mi][3],
                             b[ni][0], b[ni][1]);
        }
    }

    // epilogue: out[orig] = x[orig] + acc + bu[t]
    const float* bup = bu + (size_t)t * SIZE + n0;
#pragma unroll
    for (int mi = 0; mi < 2; mi++) {
        int r0 = wm * 32 + mi * 16 + g;
        int r1 = r0 + 8;
#pragma unroll
        for (int ni = 0; ni < 8; ni++) {
            int col = wn * 64 + ni * 8 + tg * 2;
            float b0 = bup[col], b1 = bup[col + 1];
            if (r0 < rows) {
                size_t o = (size_t)s_orig[r0] * SIZE + n0 + col;
                out[o]     = x[o]     + c[mi][ni][0] + b0;
                out[o + 1] = x[o + 1] + c[mi][ni][1] + b1;
            }
            if (r1 < rows) {
                size_t o = (size_t)s_orig[r1] * SIZE + n0 + col;
                out[o]     = x[o]     + c[mi][ni][2] + b0;
                out[o + 1] = x[o + 1] + c[mi][ni][3] + b1;
            }
        }
    }
}

// ---------------- launch ----------------
extern "C" void kernel_launch(void* const* d_in, const int* in_sizes, int n_in,
                              void* d_out, int out_size) {
    const float* x       = (const float*)d_in[0];
    const int*   task_id = (const int*)d_in[1];
    const float* Wd      = (const float*)d_in[2];
    const float* bd      = (const float*)d_in[3];
    const float* Wu      = (const float*)d_in[4];
    const float* bu      = (const float*)d_in[5];
    float*       out     = (float*)d_out;
    const int B = in_sizes[1];

    prep_kernel<<<1, 256>>>(task_id, B);

    const int smemD = D_STAGES * (64 * D_ASTRIDE + 32 * D_BSTRIDE) * 4;   // ~55 KB
    cudaFuncSetAttribute(down_kernel, cudaFuncAttributeMaxDynamicSharedMemorySize, smemD);
    dim3 gD(NDOWN / 64, B / 64 + NT);
    down_kernel<<<gD, 128, smemD>>>(x, Wd, bd, B);

    const int smemU = U_STAGES * (128 * U_ASTRIDE + 32 * U_BSTRIDE) * 4;  // ~105 KB
    cudaFuncSetAttribute(up_kernel, cudaFuncAttributeMaxDynamicSharedMemorySize, smemU);
    dim3 gU(SIZE / 128, B / 128 + NT);
    up_kernel<<<gU, 256, smemU>>>(x, Wu, bu, out, B);
}

// round 3
// speedup vs baseline: 1.0852x; 1.0852x over previous
#include <cuda_runtime.h>
#include <cstdint>

#define SIZE   4096
#define NDOWN  256
#define NT     16
#define MAXB   4096
#define MTILE  128
#define KSPLIT 8
#define KCHUNK (SIZE / KSPLIT)   // 512

// ---------------- device scratch ----------------
__device__ int   g_offsets[NT + 1];
__device__ int   g_sorted[MAXB];
__device__ int   g_rowtask[MAXB];
__device__ int   g_work_t[MAXB / MTILE + NT];
__device__ int   g_work_m0[MAXB / MTILE + NT];
__device__ int   g_nwork;
__device__ float g_part[KSPLIT][MAXB][NDOWN];   // split-K partials (~33MB)
__device__ float g_act[(size_t)MAXB * NDOWN];

// ---------------- helpers ----------------
__device__ __forceinline__ uint32_t smem_u32(const void* p) {
    return (uint32_t)__cvta_generic_to_shared(p);
}
__device__ __forceinline__ void cp_async16(uint32_t dst, const void* src, bool pred) {
    int sz = pred ? 16 : 0;
    asm volatile("cp.async.cg.shared.global [%0], [%1], 16, %2;\n"
                 :: "r"(dst), "l"(src), "r"(sz) : "memory");
}
__device__ __forceinline__ void cp_commit() {
    asm volatile("cp.async.commit_group;\n" ::: "memory");
}
__device__ __forceinline__ void cp_wait1() {
    asm volatile("cp.async.wait_group 1;\n" ::: "memory");
}
__device__ __forceinline__ void mma_tf32(float& c0, float& c1, float& c2, float& c3,
                                         uint32_t a0, uint32_t a1, uint32_t a2, uint32_t a3,
                                         uint32_t b0, uint32_t b1) {
    asm volatile(
        "mma.sync.aligned.m16n8k8.row.col.f32.tf32.tf32.f32 "
        "{%0,%1,%2,%3}, {%4,%5,%6,%7}, {%8,%9}, {%0,%1,%2,%3};\n"
        : "+f"(c0), "+f"(c1), "+f"(c2), "+f"(c3)
        : "r"(a0), "r"(a1), "r"(a2), "r"(a3), "r"(b0), "r"(b1));
}

// ---------------- phase A: counting sort + worklist ----------------
__global__ void prep_kernel(const int* __restrict__ task_id, int B) {
    __shared__ int cnt[NT];
    __shared__ int off[NT + 1];
    __shared__ int cur[NT];
    int tid = threadIdx.x;
    if (tid < NT) cnt[tid] = 0;
    __syncthreads();
    for (int i = tid; i < B; i += blockDim.x)
        atomicAdd(&cnt[task_id[i]], 1);
    __syncthreads();
    if (tid == 0) {
        int s = 0, nw = 0;
        for (int t = 0; t < NT; t++) {
            off[t] = s;
            for (int m = s; m < s + cnt[t]; m += MTILE) {
                g_work_t[nw] = t; g_work_m0[nw] = m; nw++;
            }
            s += cnt[t];
        }
        off[NT] = s;
        g_nwork = nw;
    }
    __syncthreads();
    if (tid <= NT) g_offsets[tid] = off[tid];
    if (tid < NT)  cur[tid] = off[tid];
    __syncthreads();
    for (int i = tid; i < B; i += blockDim.x) {
        int t = task_id[i];
        int p = atomicAdd(&cur[t], 1);
        g_sorted[p]  = i;
        g_rowtask[p] = t;
    }
}

// ---------------- phase B: down-proj split-K (tf32 mma) ----------------
// Tile: 128(M) x 256(N) x 32(K-step), K-chunk 512 per CTA, 512 threads
// = 16 warps (4x4 of 32x64 warp tiles), 3-stage cp.async pipeline.
#define D_ASTRIDE 36    // 32 + 4   (lane addr = 4g+tg mod 32 -> conflict-free)
#define D_BSTRIDE 264   // 256 + 8  (lane addr = 8tg+g mod 32 -> conflict-free)
#define D_STAGES  3
#define D_SMEM (D_STAGES * (MTILE * D_ASTRIDE + 32 * D_BSTRIDE) * 4)

__global__ void __launch_bounds__(512, 1) down_kernel(const float* __restrict__ x,
                                                      const float* __restrict__ Wd) {
    if ((int)blockIdx.y >= g_nwork) return;
    const int t    = g_work_t[blockIdx.y];
    const int m0   = g_work_m0[blockIdx.y];
    const int rows = min(MTILE, g_offsets[t + 1] - m0);
    const int ks0  = blockIdx.x * KCHUNK;

    extern __shared__ float smem[];
    float* As = smem;                                    // [3][128][36]
    float* Bs = smem + D_STAGES * MTILE * D_ASTRIDE;     // [3][32][264]
    __shared__ int s_idx[MTILE];

    const int tid = threadIdx.x;
    if (tid < MTILE) s_idx[tid] = (tid < rows) ? g_sorted[m0 + tid] : -1;
    __syncthreads();

    const uint32_t aU = smem_u32(As);
    const uint32_t bU = smem_u32(Bs);
    const float*   wsrc = Wd + (size_t)t * SIZE * NDOWN;

    auto fill = [&](int j) {
        const int s  = j % D_STAGES;
        const int k0 = ks0 + j * 32;
#pragma unroll
        for (int i = 0; i < 2; i++) {            // A: 128x32 = 1024 float4
            int f = tid + i * 512;
            int r = f >> 3, c = (f & 7) << 2;
            int idx = s_idx[r];
            const float* src = x + (size_t)(idx < 0 ? 0 : idx) * SIZE + k0 + c;
            cp_async16(aU + (uint32_t)(((s * MTILE + r) * D_ASTRIDE + c) * 4), src, idx >= 0);
        }
#pragma unroll
        for (int i = 0; i < 4; i++) {            // B: 32x256 = 2048 float4
            int f = tid + i * 512;
            int r = f >> 6, c = (f & 63) << 2;
            const float* src = wsrc + (size_t)(k0 + r) * NDOWN + c;
            cp_async16(bU + (uint32_t)(((s * 32 + r) * D_BSTRIDE + c) * 4), src, true);
        }
        cp_commit();
    };

    float c[2][8][4] = {};
    const int lane = tid & 31, wid = tid >> 5;
    const int g = lane >> 2, tg = lane & 3;
    const int wm = wid >> 2, wn = wid & 3;       // 4x4 warps

    const int NIT = KCHUNK / 32;   // 16
    fill(0);
    fill(1);

    for (int it = 0; it < NIT; ++it) {
        cp_wait1();
        __syncthreads();
        const int buf = it % D_STAGES;
        const float* A  = As + buf * MTILE * D_ASTRIDE;
        const float* Bt = Bs + buf * 32 * D_BSTRIDE;
        if (it + 2 < NIT) fill(it + 2);
        else              cp_commit();
#pragma unroll
        for (int ks = 0; ks < 4; ++ks) {
            uint32_t a[2][4], b[8][2];
            const int k = ks * 8 + tg;
#pragma unroll
            for (int mi = 0; mi < 2; mi++) {
                int r = wm * 32 + mi * 16 + g;
                a[mi][0] = __float_as_uint(A[r * D_ASTRIDE + k]);
                a[mi][1] = __float_as_uint(A[(r + 8) * D_ASTRIDE + k]);
                a[mi][2] = __float_as_uint(A[r * D_ASTRIDE + k + 4]);
                a[mi][3] = __float_as_uint(A[(r + 8) * D_ASTRIDE + k + 4]);
            }
#pragma unroll
            for (int ni = 0; ni < 8; ni++) {
                int n = wn * 64 + ni * 8 + g;
                b[ni][0] = __float_as_uint(Bt[k * D_BSTRIDE + n]);
                b[ni][1] = __float_as_uint(Bt[(k + 4) * D_BSTRIDE + n]);
            }
#pragma unroll
            for (int mi = 0; mi < 2; mi++)
#pragma unroll
                for (int ni = 0; ni < 8; ni++)
                    mma_tf32(c[mi][ni][0], c[mi][ni][1], c[mi][ni][2], c[mi][ni][3],
                             a[mi][0], a[mi][1], a[mi][2], a[mi][3],
                             b[ni][0], b[ni][1]);
        }
    }

    // write split-K partials (sorted layout)
    float* pbase = &g_part[blockIdx.x][0][0];
#pragma unroll
    for (int mi = 0; mi < 2; mi++) {
        int r0 = wm * 32 + mi * 16 + g;
        int r1 = r0 + 8;
#pragma unroll
        for (int ni = 0; ni < 8; ni++) {
            int col = wn * 64 + ni * 8 + tg * 2;
            if (r0 < rows)
                *(float2*)(pbase + (size_t)(m0 + r0) * NDOWN + col) =
                    make_float2(c[mi][ni][0], c[mi][ni][1]);
            if (r1 < rows)
                *(float2*)(pbase + (size_t)(m0 + r1) * NDOWN + col) =
                    make_float2(c[mi][ni][2], c[mi][ni][3]);
        }
    }
}

// ---------------- phase B2: reduce partials + bias + silu ----------------
__global__ void __launch_bounds__(1024) reduce_kernel(const float* __restrict__ bd, int B) {
    int gidx = blockIdx.x * 1024 + threadIdx.x;
    if (gidx >= B * NDOWN) return;
    int pos = gidx >> 8;          // /256
    int col = gidx & (NDOWN - 1);
    float s = 0.f;
#pragma unroll
    for (int k = 0; k < KSPLIT; k++)
        s += g_part[k][pos][col];
    s += bd[g_rowtask[pos] * NDOWN + col];
    g_act[gidx] = s / (1.f + __expf(-s));
}

// ---------------- phase C: up-proj + bias + residual ----------------
#define U_ASTRIDE 36    // 32 + 4
#define U_BSTRIDE 136   // 128 + 8
#define U_STAGES  3
#define U_SMEM (U_STAGES * (128 * U_ASTRIDE + 32 * U_BSTRIDE) * 4)

__global__ void __launch_bounds__(256) up_kernel(const float* __restrict__ x,
                                                 const float* __restrict__ Wu,
                                                 const float* __restrict__ bu,
                                                 float* __restrict__ out) {
    if ((int)blockIdx.y >= g_nwork) return;
    const int t    = g_work_t[blockIdx.y];
    const int m0   = g_work_m0[blockIdx.y];
    const int rows = min(128, g_offsets[t + 1] - m0);
    const int n0   = blockIdx.x * 128;

    extern __shared__ float smem[];
    float* As = smem;                                 // [3][128][36]
    float* Bs = smem + U_STAGES * 128 * U_ASTRIDE;    // [3][32][136]
    __shared__ int s_orig[128];

    const int tid = threadIdx.x;
    if (tid < 128) s_orig[tid] = (tid < rows) ? g_sorted[m0 + tid] : 0;

    const uint32_t aU = smem_u32(As);
    const uint32_t bU = smem_u32(Bs);
    const size_t   wbase = (size_t)t * NDOWN * SIZE + n0;

    auto fill = [&](int j) {
        const int s  = j % U_STAGES;
        const int k0 = j * 32;
#pragma unroll
        for (int i = 0; i < 4; i++) {
            int f = tid + i * 256;
            int r = f >> 3, kc = (f & 7) << 2;
            const float* src = g_act + (size_t)(m0 + r) * NDOWN + (k0 + kc);
            cp_async16(aU + (uint32_t)(((s * 128 + r) * U_ASTRIDE + kc) * 4), src, true);
        }
#pragma unroll
        for (int i = 0; i < 4; i++) {
            int f = tid + i * 256;
            int r = f >> 5, nc = (f & 31) << 2;
            const float* src = Wu + wbase + (size_t)(k0 + r) * SIZE + nc;
            cp_async16(bU + (uint32_t)(((s * 32 + r) * U_BSTRIDE + nc) * 4), src, true);
        }
        cp_commit();
    };

    float c[2][8][4] = {};
    const int lane = tid & 31, wid = tid >> 5;
    const int g = lane >> 2, tg = lane & 3;
    const int wm = wid >> 1, wn = wid & 1;

    const int NIT = NDOWN / 32;  // 8
    fill(0);
    fill(1);

    for (int it = 0; it < NIT; ++it) {
        cp_wait1();
        __syncthreads();
        const int buf = it % U_STAGES;
        const float* A  = As + buf * 128 * U_ASTRIDE;
        const float* Bt = Bs + buf * 32 * U_BSTRIDE;
        if (it + 2 < NIT) fill(it + 2);
        else              cp_commit();
#pragma unroll
        for (int ks = 0; ks < 4; ++ks) {
            uint32_t a[2][4], b[8][2];
            const int k = ks * 8 + tg;
#pragma unroll
            for (int mi = 0; mi < 2; mi++) {
                int r = wm * 32 + mi * 16 + g;
                a[mi][0] = __float_as_uint(A[r * U_ASTRIDE + k]);
                a[mi][1] = __float_as_uint(A[(r + 8) * U_ASTRIDE + k]);
                a[mi][2] = __float_as_uint(A[r * U_ASTRIDE + k + 4]);
                a[mi][3] = __float_as_uint(A[(r + 8) * U_ASTRIDE + k + 4]);
            }
#pragma unroll
            for (int ni = 0; ni < 8; ni++) {
                int n = wn * 64 + ni * 8 + g;
                b[ni][0] = __float_as_uint(Bt[k * U_BSTRIDE + n]);
                b[ni][1] = __float_as_uint(Bt[(k + 4) * U_BSTRIDE + n]);
            }
#pragma unroll
            for (int mi = 0; mi < 2; mi++)
#pragma unroll
                for (int ni = 0; ni < 8; ni++)
                    mma_tf32(c[mi][ni][0], c[mi][ni][1], c[mi][ni][2], c[mi][ni][3],
                             a[mi][0], a[mi][1], a[mi][2], a[mi][3],
                             b[ni][0], b[ni][1]);
        }
    }

    // epilogue: out[orig] = x[orig] + acc + bu[t]
    const float* bup = bu + (size_t)t * SIZE + n0;
#pragma unroll
    for (int mi = 0; mi < 2; mi++) {
        int r0 = wm * 32 + mi * 16 + g;
        int r1 = r0 + 8;
#pragma unroll
        for (int ni = 0; ni < 8; ni++) {
            int col = wn * 64 + ni * 8 + tg * 2;
            float b0 = bup[col], b1 = bup[col + 1];
            if (r0 < rows) {
                size_t o = (size_t)s_orig[r0] * SIZE + n0 + col;
                out[o]     = x[o]     + c[mi][ni][0] + b0;
                out[o + 1] = x[o + 1] + c[mi][ni][1] + b1;
            }
            if (r1 < rows) {
                size_t o = (size_t)s_orig[r1] * SIZE + n0 + col;
                out[o]     = x[o]     + c[mi][ni][2] + b0;
                out[o + 1] = x[o + 1] + c[mi][ni][3] + b1;
            }
        }
    }
}

// ---------------- launch ----------------
extern "C" void kernel_launch(void* const* d_in, const int* in_sizes, int n_in,
                              void* d_out, int out_size) {
    const float* x       = (const float*)d_in[0];
    const int*   task_id = (const int*)d_in[1];
    const float* Wd      = (const float*)d_in[2];
    const float* bd      = (const float*)d_in[3];
    const float* Wu      = (const float*)d_in[4];
    const float* bu      = (const float*)d_in[5];
    float*       out     = (float*)d_out;
    const int B = in_sizes[1];

    prep_kernel<<<1, 1024>>>(task_id, B);

    cudaFuncSetAttribute(down_kernel, cudaFuncAttributeMaxDynamicSharedMemorySize, D_SMEM);
    cudaFuncSetAttribute(up_kernel,   cudaFuncAttributeMaxDynamicSharedMemorySize, U_SMEM);

    const int maxWork = B / MTILE + NT;
    dim3 gD(KSPLIT, maxWork);
    down_kernel<<<gD, 512, D_SMEM>>>(x, Wd);

    reduce_kernel<<<(B * NDOWN + 1023) / 1024, 1024>>>(bd, B);

    dim3 gU(SIZE / 128, maxWork);
    up_kernel<<<gU, 256, U_SMEM>>>(x, Wu, bu, out);
}

// round 4
// speedup vs baseline: 1.2530x; 1.1547x over previous
#include <cuda_runtime.h>
#include <cuda_bf16.h>
#include <cstdint>

#define SIZE   4096
#define NDOWN  256
#define NT     16
#define MAXB   4096
#define MTILE  128
#define KSPLIT 8
#define KCHUNK (SIZE / KSPLIT)   // 512
#define KTILE  32

// ---------------- device scratch ----------------
__device__ int   g_offsets[NT + 1];
__device__ int   g_sorted[MAXB];
__device__ int   g_rowtask[MAXB];
__device__ int   g_work_t[MAXB / MTILE + NT];
__device__ int   g_work_m0[MAXB / MTILE + NT];
__device__ int   g_nwork;
__device__ float g_part[KSPLIT][MAXB][NDOWN];          // split-K partials
__device__ __nv_bfloat16 g_act[(size_t)MAXB * NDOWN];  // silu output, bf16

// ---------------- helpers ----------------
__device__ __forceinline__ uint32_t smem_u32(const void* p) {
    return (uint32_t)__cvta_generic_to_shared(p);
}
__device__ __forceinline__ void cp_async16(uint32_t dst, const void* src) {
    asm volatile("cp.async.cg.shared.global [%0], [%1], 16;\n"
                 :: "r"(dst), "l"(src) : "memory");
}
__device__ __forceinline__ void cp_commit() {
    asm volatile("cp.async.commit_group;\n" ::: "memory");
}
__device__ __forceinline__ void cp_wait1() {
    asm volatile("cp.async.wait_group 1;\n" ::: "memory");
}
__device__ __forceinline__ void cp_wait0() {
    asm volatile("cp.async.wait_group 0;\n" ::: "memory");
}
__device__ __forceinline__ uint32_t pack_bf16(float lo, float hi) {
    uint32_t r;
    asm("cvt.rn.bf16x2.f32 %0, %1, %2;" : "=r"(r) : "f"(hi), "f"(lo));
    return r;
}
__device__ __forceinline__ uint4 cvt_f4x2(float4 a, float4 b) {
    uint4 u;
    u.x = pack_bf16(a.x, a.y); u.y = pack_bf16(a.z, a.w);
    u.z = pack_bf16(b.x, b.y); u.w = pack_bf16(b.z, b.w);
    return u;
}
__device__ __forceinline__ void ldsm4(uint32_t& r0, uint32_t& r1, uint32_t& r2, uint32_t& r3,
                                      uint32_t addr) {
    asm volatile("ldmatrix.sync.aligned.m8n8.x4.shared.b16 {%0,%1,%2,%3}, [%4];"
                 : "=r"(r0), "=r"(r1), "=r"(r2), "=r"(r3) : "r"(addr));
}
__device__ __forceinline__ void ldsm4t(uint32_t& r0, uint32_t& r1, uint32_t& r2, uint32_t& r3,
                                       uint32_t addr) {
    asm volatile("ldmatrix.sync.aligned.m8n8.x4.trans.shared.b16 {%0,%1,%2,%3}, [%4];"
                 : "=r"(r0), "=r"(r1), "=r"(r2), "=r"(r3) : "r"(addr));
}
__device__ __forceinline__ void mma_bf16(float& c0, float& c1, float& c2, float& c3,
                                         uint32_t a0, uint32_t a1, uint32_t a2, uint32_t a3,
                                         uint32_t b0, uint32_t b1) {
    asm volatile(
        "mma.sync.aligned.m16n8k16.row.col.f32.bf16.bf16.f32 "
        "{%0,%1,%2,%3}, {%4,%5,%6,%7}, {%8,%9}, {%0,%1,%2,%3};\n"
        : "+f"(c0), "+f"(c1), "+f"(c2), "+f"(c3)
        : "r"(a0), "r"(a1), "r"(a2), "r"(a3), "r"(b0), "r"(b1));
}

// warp-tile compute: 32(M) x 64(N) x 32(K), bf16 via ldmatrix
// A smem: [128][AST] bf16 row-major (m,k).  B smem: [32][BST] bf16 (k,n).
template <int AST, int BST>
__device__ __forceinline__ void compute_tile(uint32_t aSlot, uint32_t bSlot,
                                             int lane, int wm, int wn,
                                             float c[2][8][4]) {
#pragma unroll
    for (int ks = 0; ks < 2; ++ks) {
        uint32_t a[2][4];
#pragma unroll
        for (int mi = 0; mi < 2; mi++) {
            uint32_t addr = aSlot + 2u * ((wm * 32 + mi * 16 + (lane & 15)) * AST
                                          + ks * 16 + (lane >> 4) * 8);
            ldsm4(a[mi][0], a[mi][1], a[mi][2], a[mi][3], addr);
        }
        uint32_t b[8][2];
#pragma unroll
        for (int nb = 0; nb < 4; nb++) {
            uint32_t addr = bSlot + 2u * ((ks * 16 + ((lane >> 3) & 1) * 8 + (lane & 7)) * BST
                                          + wn * 64 + nb * 16 + (lane >> 4) * 8);
            ldsm4t(b[2 * nb][0], b[2 * nb][1], b[2 * nb + 1][0], b[2 * nb + 1][1], addr);
        }
#pragma unroll
        for (int mi = 0; mi < 2; mi++)
#pragma unroll
            for (int ni = 0; ni < 8; ni++)
                mma_bf16(c[mi][ni][0], c[mi][ni][1], c[mi][ni][2], c[mi][ni][3],
                         a[mi][0], a[mi][1], a[mi][2], a[mi][3],
                         b[ni][0], b[ni][1]);
    }
}

// ---------------- phase A: counting sort + worklist ----------------
__global__ void prep_kernel(const int* __restrict__ task_id, int B) {
    __shared__ int cnt[NT];
    __shared__ int off[NT + 1];
    __shared__ int cur[NT];
    int tid = threadIdx.x;
    if (tid < NT) cnt[tid] = 0;
    __syncthreads();
    for (int i = tid; i < B; i += blockDim.x)
        atomicAdd(&cnt[task_id[i]], 1);
    __syncthreads();
    if (tid == 0) {
        int s = 0, nw = 0;
        for (int t = 0; t < NT; t++) {
            off[t] = s;
            for (int m = s; m < s + cnt[t]; m += MTILE) {
                g_work_t[nw] = t; g_work_m0[nw] = m; nw++;
            }
            s += cnt[t];
        }
        off[NT] = s;
        g_nwork = nw;
    }
    __syncthreads();
    if (tid <= NT) g_offsets[tid] = off[tid];
    if (tid < NT)  cur[tid] = off[tid];
    __syncthreads();
    for (int i = tid; i < B; i += blockDim.x) {
        int t = task_id[i];
        int p = atomicAdd(&cur[t], 1);
        g_sorted[p]  = i;
        g_rowtask[p] = t;
    }
}

// ---------------- phase B: down-proj split-K (bf16 mma) ----------------
// 128(M) x 256(N) x 32(K-step), K-chunk 512/CTA, 512 thr = 16 warps (4x4),
// manual double-buffer: LDG f32 -> cvt bf16 -> STS.
#define D_AST 40    // 32 + 8 bf16  (80B row, LDSM conflict-free)
#define D_BST 264   // 256 + 8 bf16 (528B row)
#define D_SMEM (2 * (MTILE * D_AST + 32 * D_BST) * 2)

__global__ void __launch_bounds__(512, 1) down_kernel(const float* __restrict__ x,
                                                      const float* __restrict__ Wd) {
    if ((int)blockIdx.y >= g_nwork) return;
    const int t    = g_work_t[blockIdx.y];
    const int m0   = g_work_m0[blockIdx.y];
    const int rows = min(MTILE, g_offsets[t + 1] - m0);
    const int ks0  = blockIdx.x * KCHUNK;

    extern __shared__ __align__(16) char smem[];
    __shared__ int s_idx[MTILE];

    const int tid = threadIdx.x;
    if (tid < MTILE) s_idx[tid] = (tid < rows) ? g_sorted[m0 + tid] : -1;
    __syncthreads();

    const uint32_t aU = smem_u32(smem);
    const uint32_t bU = aU + 2u * 2 * MTILE * D_AST;
    const float*   wsrc = Wd + (size_t)t * SIZE * NDOWN;

    // per-thread load geometry
    const int ar = tid >> 2,   ac = (tid & 3) * 8;     // A: row, col8
    const int bk = tid >> 4,   bn = (tid & 15) * 16;   // B: k-row, n0
    const int aidx = s_idx[ar];
    const float* asrc = x + (size_t)(aidx < 0 ? 0 : aidx) * SIZE + ac;
    const float* bsrc = wsrc + (size_t)bk * NDOWN + bn;

    float4 ra[2], rb[4];
    auto loadA = [&](int j) {
        const float* p = asrc + ks0 + j * KTILE;
        ra[0] = *(const float4*)(p);
        ra[1] = *(const float4*)(p + 4);
    };
    auto loadB = [&](int j) {
        const float* p = bsrc + (size_t)(ks0 + j * KTILE) * NDOWN;
        rb[0] = *(const float4*)(p);
        rb[1] = *(const float4*)(p + 4);
        rb[2] = *(const float4*)(p + 8);
        rb[3] = *(const float4*)(p + 12);
    };
    auto store = [&](int s) {
        *(uint4*)(smem + 2u * ((uint32_t)s * MTILE * D_AST + ar * D_AST + ac)) =
            cvt_f4x2(ra[0], ra[1]);
        char* bbase = smem + 2u * 2 * MTILE * D_AST;
        *(uint4*)(bbase + 2u * ((uint32_t)s * 32 * D_BST + bk * D_BST + bn)) =
            cvt_f4x2(rb[0], rb[1]);
        *(uint4*)(bbase + 2u * ((uint32_t)s * 32 * D_BST + bk * D_BST + bn + 8)) =
            cvt_f4x2(rb[2], rb[3]);
    };

    float c[2][8][4] = {};
    const int lane = tid & 31, wid = tid >> 5;
    const int wm = wid >> 2, wn = wid & 3;

    const int NIT = KCHUNK / KTILE;   // 16
    loadA(0); loadB(0);
    store(0);
    loadA(1); loadB(1);
    __syncthreads();

    for (int it = 0; it < NIT; ++it) {
        const int buf = it & 1;
        compute_tile<D_AST, D_BST>(aU + 2u * (uint32_t)buf * MTILE * D_AST,
                                   bU + 2u * (uint32_t)buf * 32 * D_BST,
                                   lane, wm, wn, c);
        if (it + 1 < NIT) store((it + 1) & 1);
        if (it + 2 < NIT) { loadA(it + 2); loadB(it + 2); }
        __syncthreads();
    }

    // write split-K partials (sorted layout, f32)
    const int g = lane >> 2, tg = lane & 3;
    float* pbase = &g_part[blockIdx.x][0][0];
#pragma unroll
    for (int mi = 0; mi < 2; mi++) {
        int r0 = wm * 32 + mi * 16 + g;
        int r1 = r0 + 8;
#pragma unroll
        for (int ni = 0; ni < 8; ni++) {
            int col = wn * 64 + ni * 8 + tg * 2;
            if (r0 < rows)
                *(float2*)(pbase + (size_t)(m0 + r0) * NDOWN + col) =
                    make_float2(c[mi][ni][0], c[mi][ni][1]);
            if (r1 < rows)
                *(float2*)(pbase + (size_t)(m0 + r1) * NDOWN + col) =
                    make_float2(c[mi][ni][2], c[mi][ni][3]);
        }
    }
}

// ---------------- phase B2: reduce partials + bias + silu -> bf16 ------------
__global__ void __launch_bounds__(1024) reduce_kernel(const float* __restrict__ bd, int B) {
    int gidx = blockIdx.x * 1024 + threadIdx.x;
    if (gidx >= B * NDOWN) return;
    int pos = gidx >> 8;
    int col = gidx & (NDOWN - 1);
    float s = 0.f;
#pragma unroll
    for (int k = 0; k < KSPLIT; k++)
        s += g_part[k][pos][col];
    s += bd[g_rowtask[pos] * NDOWN + col];
    g_act[gidx] = __float2bfloat16(s / (1.f + __expf(-s)));
}

// ---------------- phase C: up-proj + bias + residual (bf16 mma) --------------
// 128(M) x 128(N) x 32(K-step), 256 thr = 8 warps (4x2 of 32x64).
// A (g_act bf16): cp.async, 3 slots.  B (Wu f32->bf16): manual, 2 slots.
#define U_AST 40
#define U_BST 136   // 128 + 8
#define U_A_BYTES (3 * MTILE * U_AST * 2)
#define U_SMEM (U_A_BYTES + 2 * 32 * U_BST * 2)

__global__ void __launch_bounds__(256) up_kernel(const float* __restrict__ x,
                                                 const float* __restrict__ Wu,
                                                 const float* __restrict__ bu,
                                                 float* __restrict__ out) {
    if ((int)blockIdx.y >= g_nwork) return;
    const int t    = g_work_t[blockIdx.y];
    const int m0   = g_work_m0[blockIdx.y];
    const int rows = min(MTILE, g_offsets[t + 1] - m0);
    const int n0   = blockIdx.x * 128;

    extern __shared__ __align__(16) char smem[];
    __shared__ int s_orig[MTILE];

    const int tid = threadIdx.x;
    if (tid < MTILE) s_orig[tid] = (tid < rows) ? g_sorted[m0 + tid] : 0;

    const uint32_t aU = smem_u32(smem);
    const uint32_t bU = aU + U_A_BYTES;

    // A cp.async geometry: 2 x 16B per thread
    const __nv_bfloat16* asrc = g_act + (size_t)m0 * NDOWN;
    auto cpA = [&](int j) {
        const int slot = j % 3;
        const int k0 = j * KTILE;
#pragma unroll
        for (int i = 0; i < 2; i++) {
            int f = tid + i * 256;
            int r = f >> 2, seg = (f & 3) * 8;
            cp_async16(aU + 2u * ((uint32_t)slot * MTILE * U_AST + r * U_AST + seg),
                       asrc + (size_t)r * NDOWN + k0 + seg);
        }
        cp_commit();
    };

    // B manual: 16 f32 per thread
    const int bk = tid >> 3, bn = (tid & 7) * 16;
    const float* bsrc = Wu + (size_t)t * NDOWN * SIZE + n0 + (size_t)bk * SIZE + bn;
    float4 rb[4];
    auto loadB = [&](int j) {
        const float* p = bsrc + (size_t)j * KTILE * SIZE;
        rb[0] = *(const float4*)(p);
        rb[1] = *(const float4*)(p + 4);
        rb[2] = *(const float4*)(p + 8);
        rb[3] = *(const float4*)(p + 12);
    };
    auto storeB = [&](int s) {
        char* bbase = smem + U_A_BYTES;
        *(uint4*)(bbase + 2u * ((uint32_t)s * 32 * U_BST + bk * U_BST + bn)) =
            cvt_f4x2(rb[0], rb[1]);
        *(uint4*)(bbase + 2u * ((uint32_t)s * 32 * U_BST + bk * U_BST + bn + 8)) =
            cvt_f4x2(rb[2], rb[3]);
    };

    float c[2][8][4] = {};
    const int lane = tid & 31, wid = tid >> 5;
    const int wm = wid >> 1, wn = wid & 1;

    const int NIT = NDOWN / KTILE;   // 8
    cpA(0); cpA(1);
    loadB(0);
    storeB(0);
    loadB(1);
    cp_wait1();
    __syncthreads();

    for (int it = 0; it < NIT; ++it) {
        compute_tile<U_AST, U_BST>(aU + 2u * (uint32_t)(it % 3) * MTILE * U_AST,
                                   bU + 2u * (uint32_t)(it & 1) * 32 * U_BST,
                                   lane, wm, wn, c);
        if (it + 1 < NIT) storeB((it + 1) & 1);
        if (it + 2 < NIT) {
            loadB(it + 2);
            cpA(it + 2);
            cp_wait1();
        } else {
            cp_wait0();
        }
        __syncthreads();
    }

    // epilogue: out[orig] = x[orig] + acc + bu[t]
    const int g = lane >> 2, tg = lane & 3;
    const float* bup = bu + (size_t)t * SIZE + n0;
#pragma unroll
    for (int mi = 0; mi < 2; mi++) {
        int r0 = wm * 32 + mi * 16 + g;
        int r1 = r0 + 8;
#pragma unroll
        for (int ni = 0; ni < 8; ni++) {
            int col = wn * 64 + ni * 8 + tg * 2;
            float b0 = bup[col], b1 = bup[col + 1];
            if (r0 < rows) {
                size_t o = (size_t)s_orig[r0] * SIZE + n0 + col;
                out[o]     = x[o]     + c[mi][ni][0] + b0;
                out[o + 1] = x[o + 1] + c[mi][ni][1] + b1;
            }
            if (r1 < rows) {
                size_t o = (size_t)s_orig[r1] * SIZE + n0 + col;
                out[o]     = x[o]     + c[mi][ni][2] + b0;
                out[o + 1] = x[o + 1] + c[mi][ni][3] + b1;
            }
        }
    }
}

// ---------------- launch ----------------
extern "C" void kernel_launch(void* const* d_in, const int* in_sizes, int n_in,
                              void* d_out, int out_size) {
    const float* x       = (const float*)d_in[0];
    const int*   task_id = (const int*)d_in[1];
    const float* Wd      = (const float*)d_in[2];
    const float* bd      = (const float*)d_in[3];
    const float* Wu      = (const float*)d_in[4];
    const float* bu      = (const float*)d_in[5];
    float*       out     = (float*)d_out;
    const int B = in_sizes[1];

    prep_kernel<<<1, 1024>>>(task_id, B);

    cudaFuncSetAttribute(down_kernel, cudaFuncAttributeMaxDynamicSharedMemorySize, D_SMEM);
    cudaFuncSetAttribute(up_kernel,   cudaFuncAttributeMaxDynamicSharedMemorySize, U_SMEM);

    const int maxWork = B / MTILE + NT;
    dim3 gD(KSPLIT, maxWork);
    down_kernel<<<gD, 512, D_SMEM>>>(x, Wd);

    reduce_kernel<<<(B * NDOWN + 1023) / 1024, 1024>>>(bd, B);

    dim3 gU(SIZE / 128, maxWork);
    up_kernel<<<gU, 256, U_SMEM>>>(x, Wu, bu, out);
}